// round 4
// baseline (speedup 1.0000x reference)
#include <cuda_runtime.h>
#include <math.h>
#include <float.h>

#define DD 64
#define HIDC 128
#define NSEG 128
#define NMAX 10000
#define EMAX 64000

// ---------------- scratch (device globals; no allocation allowed) ----------
__device__ float g_H[EMAX * HIDC];                 // edge MLP hidden  [E,128]
__device__ float g_We[(size_t)EMAX * DD * DD];     // edge weight mats [E,4096] ~1GB
__device__ float g_h[NMAX * DD];                   // node state (out == h)
__device__ float g_agg[NMAX * DD];
__device__ float g_tmp[NMAX * DD];                 // root transform -> m
__device__ float g_gi[NMAX * 3 * DD];
__device__ float g_gh[NMAX * 3 * DD];
__device__ float g_deg[NMAX];
__device__ float g_e[NMAX];
__device__ float g_q[NSEG * DD];
__device__ float g_qstar[NSEG * 2 * DD];
__device__ float g_hl[NSEG * DD];
__device__ float g_cl[NSEG * DD];
__device__ float g_mmax[NSEG];
__device__ float g_denom[NSEG];
__device__ float g_r[NSEG * DD];
__device__ float g_wihT[2 * DD * 4 * DD];          // [128][256]
__device__ float g_whhT[DD * 4 * DD];              // [64][256]
__device__ float g_y1[NSEG * DD];

// ---------------- generic tiled GEMM: C[M,N] = A[M,K] @ B[N,K]^T (+bias)(relu)
__global__ void gemm_bt(const float* __restrict__ A, const float* __restrict__ B,
                        const float* __restrict__ bias, float* __restrict__ C,
                        int M, int N, int K, int do_relu)
{
    __shared__ float As[64][65];
    __shared__ float Bs[64][65];
    int tid = threadIdx.x;
    int tx = tid & 15;       // n-quad
    int ty = tid >> 4;       // m-quad
    int mBase = blockIdx.y * 64;
    int nBase = blockIdx.x * 64;

    float acc[4][4];
#pragma unroll
    for (int i = 0; i < 4; i++)
#pragma unroll
        for (int j = 0; j < 4; j++) acc[i][j] = 0.f;

    for (int k0 = 0; k0 < K; k0 += 64) {
        for (int l = tid; l < 64 * 64; l += 256) {
            int r = l >> 6, c = l & 63;
            int gm = mBase + r, gk = k0 + c;
            As[r][c] = (gm < M && gk < K) ? A[(size_t)gm * K + gk] : 0.f;
        }
        for (int l = tid; l < 64 * 64; l += 256) {
            int r = l >> 6, c = l & 63;
            int gn = nBase + r, gk = k0 + c;
            Bs[r][c] = (gn < N && gk < K) ? B[(size_t)gn * K + gk] : 0.f;
        }
        __syncthreads();
#pragma unroll
        for (int k = 0; k < 64; k++) {
            float a0 = As[ty * 4 + 0][k];
            float a1 = As[ty * 4 + 1][k];
            float a2 = As[ty * 4 + 2][k];
            float a3 = As[ty * 4 + 3][k];
            float b0 = Bs[tx * 4 + 0][k];
            float b1 = Bs[tx * 4 + 1][k];
            float b2 = Bs[tx * 4 + 2][k];
            float b3 = Bs[tx * 4 + 3][k];
            acc[0][0] += a0 * b0; acc[0][1] += a0 * b1; acc[0][2] += a0 * b2; acc[0][3] += a0 * b3;
            acc[1][0] += a1 * b0; acc[1][1] += a1 * b1; acc[1][2] += a1 * b2; acc[1][3] += a1 * b3;
            acc[2][0] += a2 * b0; acc[2][1] += a2 * b1; acc[2][2] += a2 * b2; acc[2][3] += a2 * b3;
            acc[3][0] += a3 * b0; acc[3][1] += a3 * b1; acc[3][2] += a3 * b2; acc[3][3] += a3 * b3;
        }
        __syncthreads();
    }

#pragma unroll
    for (int i = 0; i < 4; i++) {
        int gm = mBase + ty * 4 + i;
        if (gm >= M) continue;
        int gn0 = nBase + tx * 4;
        if (gn0 + 3 < N) {
            float4 v;
            v.x = acc[i][0] + (bias ? bias[gn0 + 0] : 0.f);
            v.y = acc[i][1] + (bias ? bias[gn0 + 1] : 0.f);
            v.z = acc[i][2] + (bias ? bias[gn0 + 2] : 0.f);
            v.w = acc[i][3] + (bias ? bias[gn0 + 3] : 0.f);
            if (do_relu) {
                v.x = fmaxf(v.x, 0.f); v.y = fmaxf(v.y, 0.f);
                v.z = fmaxf(v.z, 0.f); v.w = fmaxf(v.w, 0.f);
            }
            *reinterpret_cast<float4*>(&C[(size_t)gm * N + gn0]) = v;
        } else {
#pragma unroll
            for (int j = 0; j < 4; j++) {
                int gn = gn0 + j;
                if (gn >= N) continue;
                float v = acc[i][j] + (bias ? bias[gn] : 0.f);
                if (do_relu) v = fmaxf(v, 0.f);
                C[(size_t)gm * N + gn] = v;
            }
        }
    }
}

// ---------------- degree ----------------
__global__ void deg_kernel(const int* __restrict__ dst, float* __restrict__ deg, int E)
{
    int i = blockIdx.x * blockDim.x + threadIdx.x;
    if (i < E) atomicAdd(&deg[dst[i]], 1.f);
}

// ---------------- per-edge message + scatter ----------------
__global__ void msg_kernel(const float* __restrict__ h, const float* __restrict__ We,
                           const int* __restrict__ src, const int* __restrict__ dst,
                           float* __restrict__ agg)
{
    int e = blockIdx.x;
    int o = threadIdx.x;               // 64 threads
    __shared__ float xs[DD];
    int s = src[e];
    xs[o] = h[s * DD + o];
    __syncthreads();
    const float* w = We + (size_t)e * DD * DD + o;
    float acc = 0.f;
#pragma unroll
    for (int i = 0; i < DD; i++) acc += xs[i] * w[i * DD];
    atomicAdd(&agg[dst[e] * DD + o], acc);
}

// ---------------- m = relu(root + agg/deg) ----------------
__global__ void m_kernel(float* __restrict__ tmp, const float* __restrict__ agg,
                         const float* __restrict__ deg, int total)
{
    int idx = blockIdx.x * blockDim.x + threadIdx.x;
    if (idx >= total) return;
    int n = idx >> 6;
    float v = tmp[idx] + agg[idx] / fmaxf(deg[n], 1.f);
    tmp[idx] = fmaxf(v, 0.f);
}

// ---------------- GRU elementwise ----------------
__device__ __forceinline__ float sigm(float x) { return 1.f / (1.f + expf(-x)); }

__global__ void gru_kernel(const float* __restrict__ gi, const float* __restrict__ gh,
                           float* __restrict__ h, int total)
{
    int idx = blockIdx.x * blockDim.x + threadIdx.x;
    if (idx >= total) return;
    int n = idx >> 6, d = idx & 63;
    const float* gin = gi + (size_t)n * 3 * DD;
    const float* ghn = gh + (size_t)n * 3 * DD;
    float r = sigm(gin[d] + ghn[d]);
    float z = sigm(gin[DD + d] + ghn[DD + d]);
    float nn = tanhf(gin[2 * DD + d] + r * ghn[2 * DD + d]);
    h[idx] = (1.f - z) * nn + z * h[idx];
}

// ---------------- LSTM weight transposes ----------------
__global__ void transpose_lstm(const float* __restrict__ wih, const float* __restrict__ whh,
                               float* __restrict__ wihT, float* __restrict__ whhT)
{
    int idx = blockIdx.x * blockDim.x + threadIdx.x;
    if (idx < 2 * DD * 4 * DD) {                    // 128*256
        int k = idx >> 8, j = idx & 255;
        wihT[idx] = wih[j * (2 * DD) + k];
    } else if (idx < 2 * DD * 4 * DD + DD * 4 * DD) {
        int rel = idx - 2 * DD * 4 * DD;
        int k = rel >> 8, j = rel & 255;
        whhT[rel] = whh[j * DD + k];
    }
}

// ---------------- Set2Set LSTM step ----------------
__global__ void lstm_kernel(const float* __restrict__ wihT, const float* __restrict__ whhT,
                            const float* __restrict__ b_ih, const float* __restrict__ b_hh,
                            const float* __restrict__ qstar, float* __restrict__ hl,
                            float* __restrict__ cl, float* __restrict__ q)
{
    int s = blockIdx.x;
    int j = threadIdx.x;                            // 256
    __shared__ float qs[2 * DD];
    __shared__ float hs[DD];
    __shared__ float gsh[4 * DD];
    if (j < 2 * DD) qs[j] = qstar[s * 2 * DD + j];
    if (j < DD) hs[j] = hl[s * DD + j];
    __syncthreads();
    float acc = b_ih[j] + b_hh[j];
#pragma unroll 4
    for (int k = 0; k < 2 * DD; k++) acc += qs[k] * wihT[k * 256 + j];
#pragma unroll 4
    for (int k = 0; k < DD; k++) acc += hs[k] * whhT[k * 256 + j];
    gsh[j] = acc;
    __syncthreads();
    if (j < DD) {
        float ig = sigm(gsh[j]);
        float fg = sigm(gsh[DD + j]);
        float gg = tanhf(gsh[2 * DD + j]);
        float og = sigm(gsh[3 * DD + j]);
        float c = fg * cl[s * DD + j] + ig * gg;
        cl[s * DD + j] = c;
        float hv = og * tanhf(c);
        hl[s * DD + j] = hv;
        q[s * DD + j] = hv;
    }
}

// ---------------- Set2Set per-step scratch init ----------------
__global__ void init_step(float* __restrict__ mmax, float* __restrict__ denom,
                          float* __restrict__ r)
{
    int idx = blockIdx.x * blockDim.x + threadIdx.x;
    if (idx < NSEG * DD) r[idx] = 0.f;
    if (idx < NSEG) { mmax[idx] = -FLT_MAX; denom[idx] = 0.f; }
}

__device__ void atomicMaxF(float* addr, float v)
{
    int old = __float_as_int(*addr);
    while (__int_as_float(old) < v) {
        int prev = atomicCAS((int*)addr, old, __float_as_int(v));
        if (prev == old) break;
        old = prev;
    }
}

// ---------------- attention scores + segment max ----------------
__global__ void escore_kernel(const float* __restrict__ h, const float* __restrict__ q,
                              const int* __restrict__ batch, float* __restrict__ e,
                              float* __restrict__ mmax, int N)
{
    int n = blockIdx.x * 4 + (threadIdx.x >> 5);
    int lane = threadIdx.x & 31;
    if (n >= N) return;
    int b = batch[n];
    float v = h[n * DD + lane] * q[b * DD + lane]
            + h[n * DD + 32 + lane] * q[b * DD + 32 + lane];
#pragma unroll
    for (int o = 16; o > 0; o >>= 1) v += __shfl_down_sync(0xffffffff, v, o);
    if (lane == 0) { e[n] = v; atomicMaxF(&mmax[b], v); }
}

// ---------------- softmax weights + weighted segment sum -------------------
__global__ void attn_kernel(const float* __restrict__ h, const float* __restrict__ e,
                            const int* __restrict__ batch, const float* __restrict__ mmax,
                            float* __restrict__ denom, float* __restrict__ r, int N)
{
    int n = blockIdx.x * 4 + (threadIdx.x >> 5);
    int lane = threadIdx.x & 31;
    if (n >= N) return;
    int b = batch[n];
    float a = expf(e[n] - mmax[b]);
    if (lane == 0) atomicAdd(&denom[b], a);
    atomicAdd(&r[b * DD + lane], a * h[n * DD + lane]);
    atomicAdd(&r[b * DD + 32 + lane], a * h[n * DD + 32 + lane]);
}

// ---------------- q_star = [q, r/denom] ----------------
__global__ void qstar_kernel(const float* __restrict__ q, const float* __restrict__ r,
                             const float* __restrict__ denom, float* __restrict__ qstar)
{
    int s = blockIdx.x;
    int j = threadIdx.x;                            // 128
    if (j < DD) {
        qstar[s * 2 * DD + j] = q[s * DD + j];
    } else {
        float dn = denom[s];
        float rv = r[s * DD + (j - DD)];
        qstar[s * 2 * DD + j] = (dn > 0.f) ? rv / dn : 0.f;
    }
}

// ---------------- final projection ----------------
__global__ void final_kernel(const float* __restrict__ y1, const float* __restrict__ w2,
                             const float* __restrict__ b2, float* __restrict__ out)
{
    int s = blockIdx.x;
    int lane = threadIdx.x;                         // 32
    float v = y1[s * DD + lane] * w2[lane] + y1[s * DD + 32 + lane] * w2[32 + lane];
#pragma unroll
    for (int o = 16; o > 0; o >>= 1) v += __shfl_down_sync(0xffffffff, v, o);
    if (lane == 0) out[s] = v + b2[0];
}

// ============================================================================
extern "C" void kernel_launch(void* const* d_in, const int* in_sizes, int n_in,
                              void* d_out, int out_size)
{
    const float* x        = (const float*)d_in[0];
    const float* ea       = (const float*)d_in[1];
    const float* lin0_w   = (const float*)d_in[2];
    const float* lin0_b   = (const float*)d_in[3];
    const float* nn1_w    = (const float*)d_in[4];
    const float* nn1_b    = (const float*)d_in[5];
    const float* nn2_w    = (const float*)d_in[6];
    const float* nn2_b    = (const float*)d_in[7];
    const float* root_w   = (const float*)d_in[8];
    const float* conv_b   = (const float*)d_in[9];
    const float* gru_w_ih = (const float*)d_in[10];
    const float* gru_w_hh = (const float*)d_in[11];
    const float* gru_b_ih = (const float*)d_in[12];
    const float* gru_b_hh = (const float*)d_in[13];
    const float* lstm_w_ih = (const float*)d_in[14];
    const float* lstm_w_hh = (const float*)d_in[15];
    const float* lstm_b_ih = (const float*)d_in[16];
    const float* lstm_b_hh = (const float*)d_in[17];
    const float* lin1_w   = (const float*)d_in[18];
    const float* lin1_b   = (const float*)d_in[19];
    const float* lin2_w   = (const float*)d_in[20];
    const float* lin2_b   = (const float*)d_in[21];
    const int*   eidx     = (const int*)d_in[22];
    const int*   batch    = (const int*)d_in[23];
    float* out = (float*)d_out;

    int N = in_sizes[0] / 92;
    int E = in_sizes[1] / 41;
    const int* src = eidx;
    const int* dst = eidx + E;

    float *pH, *pWe, *ph, *pagg, *ptmp, *pgi, *pgh, *pdeg, *pe;
    float *pq, *pqstar, *phl, *pcl, *pmmax, *pdenom, *pr, *pwihT, *pwhhT, *py1;
    cudaGetSymbolAddress((void**)&pH, g_H);
    cudaGetSymbolAddress((void**)&pWe, g_We);
    cudaGetSymbolAddress((void**)&ph, g_h);
    cudaGetSymbolAddress((void**)&pagg, g_agg);
    cudaGetSymbolAddress((void**)&ptmp, g_tmp);
    cudaGetSymbolAddress((void**)&pgi, g_gi);
    cudaGetSymbolAddress((void**)&pgh, g_gh);
    cudaGetSymbolAddress((void**)&pdeg, g_deg);
    cudaGetSymbolAddress((void**)&pe, g_e);
    cudaGetSymbolAddress((void**)&pq, g_q);
    cudaGetSymbolAddress((void**)&pqstar, g_qstar);
    cudaGetSymbolAddress((void**)&phl, g_hl);
    cudaGetSymbolAddress((void**)&pcl, g_cl);
    cudaGetSymbolAddress((void**)&pmmax, g_mmax);
    cudaGetSymbolAddress((void**)&pdenom, g_denom);
    cudaGetSymbolAddress((void**)&pr, g_r);
    cudaGetSymbolAddress((void**)&pwihT, g_wihT);
    cudaGetSymbolAddress((void**)&pwhhT, g_whhT);
    cudaGetSymbolAddress((void**)&py1, g_y1);

    // --- prep ---
    transpose_lstm<<<(2 * DD * 4 * DD + DD * 4 * DD + 255) / 256, 256>>>(
        lstm_w_ih, lstm_w_hh, pwihT, pwhhT);
    cudaMemsetAsync(pdeg, 0, (size_t)N * sizeof(float), 0);
    deg_kernel<<<(E + 255) / 256, 256>>>(dst, pdeg, E);

    // out = h = relu(x @ lin0_w^T + b)
    {
        dim3 g(1, (N + 63) / 64);
        gemm_bt<<<g, 256>>>(x, lin0_w, lin0_b, ph, N, DD, 92, 1);
    }
    // H = relu(ea @ nn1_w^T + b)
    {
        dim3 g(HIDC / 64, (E + 63) / 64);
        gemm_bt<<<g, 256>>>(ea, nn1_w, nn1_b, pH, E, HIDC, 41, 1);
    }
    // We = H @ nn2_w^T + b      (dominant GEMM, 67 GFLOP)
    {
        dim3 g((DD * DD) / 64, (E + 63) / 64);
        gemm_bt<<<g, 256>>>(pH, nn2_w, nn2_b, pWe, E, DD * DD, HIDC, 0);
    }

    // --- 2 conv + GRU iterations ---
    for (int c = 0; c < 2; c++) {
        cudaMemsetAsync(pagg, 0, (size_t)N * DD * sizeof(float), 0);
        msg_kernel<<<E, DD>>>(ph, pWe, src, dst, pagg);
        {
            dim3 g(1, (N + 63) / 64);
            gemm_bt<<<g, 256>>>(ph, root_w, conv_b, ptmp, N, DD, DD, 0);
        }
        m_kernel<<<(N * DD + 255) / 256, 256>>>(ptmp, pagg, pdeg, N * DD);
        {
            dim3 g(3, (N + 63) / 64);
            gemm_bt<<<g, 256>>>(ptmp, gru_w_ih, gru_b_ih, pgi, N, 3 * DD, DD, 0);
            gemm_bt<<<g, 256>>>(ph, gru_w_hh, gru_b_hh, pgh, N, 3 * DD, DD, 0);
        }
        gru_kernel<<<(N * DD + 255) / 256, 256>>>(pgi, pgh, ph, N * DD);
    }

    // --- Set2Set ---
    cudaMemsetAsync(pqstar, 0, NSEG * 2 * DD * sizeof(float), 0);
    cudaMemsetAsync(phl, 0, NSEG * DD * sizeof(float), 0);
    cudaMemsetAsync(pcl, 0, NSEG * DD * sizeof(float), 0);
    for (int s = 0; s < 3; s++) {
        lstm_kernel<<<NSEG, 256>>>(pwihT, pwhhT, lstm_b_ih, lstm_b_hh,
                                   pqstar, phl, pcl, pq);
        init_step<<<(NSEG * DD + 255) / 256, 256>>>(pmmax, pdenom, pr);
        escore_kernel<<<(N + 3) / 4, 128>>>(ph, pq, batch, pe, pmmax, N);
        attn_kernel<<<(N + 3) / 4, 128>>>(ph, pe, batch, pmmax, pdenom, pr, N);
        qstar_kernel<<<NSEG, 128>>>(pq, pr, pdenom, pqstar);
    }

    // --- head ---
    {
        dim3 g(1, (NSEG + 63) / 64);
        gemm_bt<<<g, 256>>>(pqstar, lin1_w, lin1_b, py1, NSEG, DD, 2 * DD, 1);
    }
    final_kernel<<<NSEG, 32>>>(py1, lin2_w, lin2_b, out);
}

// round 5
// speedup vs baseline: 1.0004x; 1.0004x over previous
#include <cuda_runtime.h>
#include <math.h>
#include <float.h>

#define DD 64
#define HIDC 128
#define NSEG 128
#define NMAX 10000
#define EMAX 64000

// ---------------- scratch (device globals; no allocation allowed) ----------
__device__ float g_H[EMAX * HIDC];                 // edge MLP hidden  [E,128]
__device__ float g_We[(size_t)EMAX * DD * DD];     // edge weight mats [E,4096] ~1GB
__device__ float g_h[NMAX * DD];                   // node state (out == h)
__device__ float g_agg[NMAX * DD];
__device__ float g_tmp[NMAX * DD];                 // root transform -> m
__device__ float g_gi[NMAX * 3 * DD];
__device__ float g_gh[NMAX * 3 * DD];
__device__ float g_deg[NMAX];
__device__ float g_e[NMAX];
__device__ float g_q[NSEG * DD];
__device__ float g_qstar[NSEG * 2 * DD];
__device__ float g_hl[NSEG * DD];
__device__ float g_cl[NSEG * DD];
__device__ float g_mmax[NSEG];
__device__ float g_denom[NSEG];
__device__ float g_r[NSEG * DD];
__device__ float g_wihT[2 * DD * 4 * DD];          // [128][256]
__device__ float g_whhT[DD * 4 * DD];              // [64][256]
__device__ float g_y1[NSEG * DD];

// ---------------- generic tiled GEMM: C[M,N] = A[M,K] @ B[N,K]^T (+bias)(relu)
__global__ void gemm_bt(const float* __restrict__ A, const float* __restrict__ B,
                        const float* __restrict__ bias, float* __restrict__ C,
                        int M, int N, int K, int do_relu)
{
    __shared__ float As[64][65];
    __shared__ float Bs[64][65];
    int tid = threadIdx.x;
    int tx = tid & 15;       // n-quad
    int ty = tid >> 4;       // m-quad
    int mBase = blockIdx.y * 64;
    int nBase = blockIdx.x * 64;

    float acc[4][4];
#pragma unroll
    for (int i = 0; i < 4; i++)
#pragma unroll
        for (int j = 0; j < 4; j++) acc[i][j] = 0.f;

    for (int k0 = 0; k0 < K; k0 += 64) {
        for (int l = tid; l < 64 * 64; l += 256) {
            int r = l >> 6, c = l & 63;
            int gm = mBase + r, gk = k0 + c;
            As[r][c] = (gm < M && gk < K) ? A[(size_t)gm * K + gk] : 0.f;
        }
        for (int l = tid; l < 64 * 64; l += 256) {
            int r = l >> 6, c = l & 63;
            int gn = nBase + r, gk = k0 + c;
            Bs[r][c] = (gn < N && gk < K) ? B[(size_t)gn * K + gk] : 0.f;
        }
        __syncthreads();
#pragma unroll
        for (int k = 0; k < 64; k++) {
            float a0 = As[ty * 4 + 0][k];
            float a1 = As[ty * 4 + 1][k];
            float a2 = As[ty * 4 + 2][k];
            float a3 = As[ty * 4 + 3][k];
            float b0 = Bs[tx * 4 + 0][k];
            float b1 = Bs[tx * 4 + 1][k];
            float b2 = Bs[tx * 4 + 2][k];
            float b3 = Bs[tx * 4 + 3][k];
            acc[0][0] += a0 * b0; acc[0][1] += a0 * b1; acc[0][2] += a0 * b2; acc[0][3] += a0 * b3;
            acc[1][0] += a1 * b0; acc[1][1] += a1 * b1; acc[1][2] += a1 * b2; acc[1][3] += a1 * b3;
            acc[2][0] += a2 * b0; acc[2][1] += a2 * b1; acc[2][2] += a2 * b2; acc[2][3] += a2 * b3;
            acc[3][0] += a3 * b0; acc[3][1] += a3 * b1; acc[3][2] += a3 * b2; acc[3][3] += a3 * b3;
        }
        __syncthreads();
    }

#pragma unroll
    for (int i = 0; i < 4; i++) {
        int gm = mBase + ty * 4 + i;
        if (gm >= M) continue;
        int gn0 = nBase + tx * 4;
        if (gn0 + 3 < N) {
            float4 v;
            v.x = acc[i][0] + (bias ? bias[gn0 + 0] : 0.f);
            v.y = acc[i][1] + (bias ? bias[gn0 + 1] : 0.f);
            v.z = acc[i][2] + (bias ? bias[gn0 + 2] : 0.f);
            v.w = acc[i][3] + (bias ? bias[gn0 + 3] : 0.f);
            if (do_relu) {
                v.x = fmaxf(v.x, 0.f); v.y = fmaxf(v.y, 0.f);
                v.z = fmaxf(v.z, 0.f); v.w = fmaxf(v.w, 0.f);
            }
            *reinterpret_cast<float4*>(&C[(size_t)gm * N + gn0]) = v;
        } else {
#pragma unroll
            for (int j = 0; j < 4; j++) {
                int gn = gn0 + j;
                if (gn >= N) continue;
                float v = acc[i][j] + (bias ? bias[gn] : 0.f);
                if (do_relu) v = fmaxf(v, 0.f);
                C[(size_t)gm * N + gn] = v;
            }
        }
    }
}

// ---------------- degree ----------------
__global__ void deg_kernel(const int* __restrict__ dst, float* __restrict__ deg, int E)
{
    int i = blockIdx.x * blockDim.x + threadIdx.x;
    if (i < E) atomicAdd(&deg[dst[i]], 1.f);
}

// ---------------- per-edge message + scatter ----------------
__global__ void msg_kernel(const float* __restrict__ h, const float* __restrict__ We,
                           const int* __restrict__ src, const int* __restrict__ dst,
                           float* __restrict__ agg)
{
    int e = blockIdx.x;
    int o = threadIdx.x;               // 64 threads
    __shared__ float xs[DD];
    int s = src[e];
    xs[o] = h[s * DD + o];
    __syncthreads();
    const float* w = We + (size_t)e * DD * DD + o;
    float acc = 0.f;
#pragma unroll
    for (int i = 0; i < DD; i++) acc += xs[i] * w[i * DD];
    atomicAdd(&agg[dst[e] * DD + o], acc);
}

// ---------------- m = relu(root + agg/deg) ----------------
__global__ void m_kernel(float* __restrict__ tmp, const float* __restrict__ agg,
                         const float* __restrict__ deg, int total)
{
    int idx = blockIdx.x * blockDim.x + threadIdx.x;
    if (idx >= total) return;
    int n = idx >> 6;
    float v = tmp[idx] + agg[idx] / fmaxf(deg[n], 1.f);
    tmp[idx] = fmaxf(v, 0.f);
}

// ---------------- GRU elementwise ----------------
__device__ __forceinline__ float sigm(float x) { return 1.f / (1.f + expf(-x)); }

__global__ void gru_kernel(const float* __restrict__ gi, const float* __restrict__ gh,
                           float* __restrict__ h, int total)
{
    int idx = blockIdx.x * blockDim.x + threadIdx.x;
    if (idx >= total) return;
    int n = idx >> 6, d = idx & 63;
    const float* gin = gi + (size_t)n * 3 * DD;
    const float* ghn = gh + (size_t)n * 3 * DD;
    float r = sigm(gin[d] + ghn[d]);
    float z = sigm(gin[DD + d] + ghn[DD + d]);
    float nn = tanhf(gin[2 * DD + d] + r * ghn[2 * DD + d]);
    h[idx] = (1.f - z) * nn + z * h[idx];
}

// ---------------- LSTM weight transposes ----------------
__global__ void transpose_lstm(const float* __restrict__ wih, const float* __restrict__ whh,
                               float* __restrict__ wihT, float* __restrict__ whhT)
{
    int idx = blockIdx.x * blockDim.x + threadIdx.x;
    if (idx < 2 * DD * 4 * DD) {                    // 128*256
        int k = idx >> 8, j = idx & 255;
        wihT[idx] = wih[j * (2 * DD) + k];
    } else if (idx < 2 * DD * 4 * DD + DD * 4 * DD) {
        int rel = idx - 2 * DD * 4 * DD;
        int k = rel >> 8, j = rel & 255;
        whhT[rel] = whh[j * DD + k];
    }
}

// ---------------- Set2Set LSTM step ----------------
__global__ void lstm_kernel(const float* __restrict__ wihT, const float* __restrict__ whhT,
                            const float* __restrict__ b_ih, const float* __restrict__ b_hh,
                            const float* __restrict__ qstar, float* __restrict__ hl,
                            float* __restrict__ cl, float* __restrict__ q)
{
    int s = blockIdx.x;
    int j = threadIdx.x;                            // 256
    __shared__ float qs[2 * DD];
    __shared__ float hs[DD];
    __shared__ float gsh[4 * DD];
    if (j < 2 * DD) qs[j] = qstar[s * 2 * DD + j];
    if (j < DD) hs[j] = hl[s * DD + j];
    __syncthreads();
    float acc = b_ih[j] + b_hh[j];
#pragma unroll 4
    for (int k = 0; k < 2 * DD; k++) acc += qs[k] * wihT[k * 256 + j];
#pragma unroll 4
    for (int k = 0; k < DD; k++) acc += hs[k] * whhT[k * 256 + j];
    gsh[j] = acc;
    __syncthreads();
    if (j < DD) {
        float ig = sigm(gsh[j]);
        float fg = sigm(gsh[DD + j]);
        float gg = tanhf(gsh[2 * DD + j]);
        float og = sigm(gsh[3 * DD + j]);
        float c = fg * cl[s * DD + j] + ig * gg;
        cl[s * DD + j] = c;
        float hv = og * tanhf(c);
        hl[s * DD + j] = hv;
        q[s * DD + j] = hv;
    }
}

// ---------------- Set2Set per-step scratch init ----------------
__global__ void init_step(float* __restrict__ mmax, float* __restrict__ denom,
                          float* __restrict__ r)
{
    int idx = blockIdx.x * blockDim.x + threadIdx.x;
    if (idx < NSEG * DD) r[idx] = 0.f;
    if (idx < NSEG) { mmax[idx] = -FLT_MAX; denom[idx] = 0.f; }
}

__device__ void atomicMaxF(float* addr, float v)
{
    int old = __float_as_int(*addr);
    while (__int_as_float(old) < v) {
        int prev = atomicCAS((int*)addr, old, __float_as_int(v));
        if (prev == old) break;
        old = prev;
    }
}

// ---------------- attention scores + segment max ----------------
__global__ void escore_kernel(const float* __restrict__ h, const float* __restrict__ q,
                              const int* __restrict__ batch, float* __restrict__ e,
                              float* __restrict__ mmax, int N)
{
    int n = blockIdx.x * 4 + (threadIdx.x >> 5);
    int lane = threadIdx.x & 31;
    if (n >= N) return;
    int b = batch[n];
    float v = h[n * DD + lane] * q[b * DD + lane]
            + h[n * DD + 32 + lane] * q[b * DD + 32 + lane];
#pragma unroll
    for (int o = 16; o > 0; o >>= 1) v += __shfl_down_sync(0xffffffff, v, o);
    if (lane == 0) { e[n] = v; atomicMaxF(&mmax[b], v); }
}

// ---------------- softmax weights + weighted segment sum -------------------
__global__ void attn_kernel(const float* __restrict__ h, const float* __restrict__ e,
                            const int* __restrict__ batch, const float* __restrict__ mmax,
                            float* __restrict__ denom, float* __restrict__ r, int N)
{
    int n = blockIdx.x * 4 + (threadIdx.x >> 5);
    int lane = threadIdx.x & 31;
    if (n >= N) return;
    int b = batch[n];
    float a = expf(e[n] - mmax[b]);
    if (lane == 0) atomicAdd(&denom[b], a);
    atomicAdd(&r[b * DD + lane], a * h[n * DD + lane]);
    atomicAdd(&r[b * DD + 32 + lane], a * h[n * DD + 32 + lane]);
}

// ---------------- q_star = [q, r/denom] ----------------
__global__ void qstar_kernel(const float* __restrict__ q, const float* __restrict__ r,
                             const float* __restrict__ denom, float* __restrict__ qstar)
{
    int s = blockIdx.x;
    int j = threadIdx.x;                            // 128
    if (j < DD) {
        qstar[s * 2 * DD + j] = q[s * DD + j];
    } else {
        float dn = denom[s];
        float rv = r[s * DD + (j - DD)];
        qstar[s * 2 * DD + j] = (dn > 0.f) ? rv / dn : 0.f;
    }
}

// ---------------- final projection ----------------
__global__ void final_kernel(const float* __restrict__ y1, const float* __restrict__ w2,
                             const float* __restrict__ b2, float* __restrict__ out)
{
    int s = blockIdx.x;
    int lane = threadIdx.x;                         // 32
    float v = y1[s * DD + lane] * w2[lane] + y1[s * DD + 32 + lane] * w2[32 + lane];
#pragma unroll
    for (int o = 16; o > 0; o >>= 1) v += __shfl_down_sync(0xffffffff, v, o);
    if (lane == 0) out[s] = v + b2[0];
}

// ============================================================================
extern "C" void kernel_launch(void* const* d_in, const int* in_sizes, int n_in,
                              void* d_out, int out_size)
{
    const float* x        = (const float*)d_in[0];
    const float* ea       = (const float*)d_in[1];
    const float* lin0_w   = (const float*)d_in[2];
    const float* lin0_b   = (const float*)d_in[3];
    const float* nn1_w    = (const float*)d_in[4];
    const float* nn1_b    = (const float*)d_in[5];
    const float* nn2_w    = (const float*)d_in[6];
    const float* nn2_b    = (const float*)d_in[7];
    const float* root_w   = (const float*)d_in[8];
    const float* conv_b   = (const float*)d_in[9];
    const float* gru_w_ih = (const float*)d_in[10];
    const float* gru_w_hh = (const float*)d_in[11];
    const float* gru_b_ih = (const float*)d_in[12];
    const float* gru_b_hh = (const float*)d_in[13];
    const float* lstm_w_ih = (const float*)d_in[14];
    const float* lstm_w_hh = (const float*)d_in[15];
    const float* lstm_b_ih = (const float*)d_in[16];
    const float* lstm_b_hh = (const float*)d_in[17];
    const float* lin1_w   = (const float*)d_in[18];
    const float* lin1_b   = (const float*)d_in[19];
    const float* lin2_w   = (const float*)d_in[20];
    const float* lin2_b   = (const float*)d_in[21];
    const int*   eidx     = (const int*)d_in[22];
    const int*   batch    = (const int*)d_in[23];
    float* out = (float*)d_out;

    int N = in_sizes[0] / 92;
    int E = in_sizes[1] / 41;
    const int* src = eidx;
    const int* dst = eidx + E;

    float *pH, *pWe, *ph, *pagg, *ptmp, *pgi, *pgh, *pdeg, *pe;
    float *pq, *pqstar, *phl, *pcl, *pmmax, *pdenom, *pr, *pwihT, *pwhhT, *py1;
    cudaGetSymbolAddress((void**)&pH, g_H);
    cudaGetSymbolAddress((void**)&pWe, g_We);
    cudaGetSymbolAddress((void**)&ph, g_h);
    cudaGetSymbolAddress((void**)&pagg, g_agg);
    cudaGetSymbolAddress((void**)&ptmp, g_tmp);
    cudaGetSymbolAddress((void**)&pgi, g_gi);
    cudaGetSymbolAddress((void**)&pgh, g_gh);
    cudaGetSymbolAddress((void**)&pdeg, g_deg);
    cudaGetSymbolAddress((void**)&pe, g_e);
    cudaGetSymbolAddress((void**)&pq, g_q);
    cudaGetSymbolAddress((void**)&pqstar, g_qstar);
    cudaGetSymbolAddress((void**)&phl, g_hl);
    cudaGetSymbolAddress((void**)&pcl, g_cl);
    cudaGetSymbolAddress((void**)&pmmax, g_mmax);
    cudaGetSymbolAddress((void**)&pdenom, g_denom);
    cudaGetSymbolAddress((void**)&pr, g_r);
    cudaGetSymbolAddress((void**)&pwihT, g_wihT);
    cudaGetSymbolAddress((void**)&pwhhT, g_whhT);
    cudaGetSymbolAddress((void**)&py1, g_y1);

    // --- prep ---
    transpose_lstm<<<(2 * DD * 4 * DD + DD * 4 * DD + 255) / 256, 256>>>(
        lstm_w_ih, lstm_w_hh, pwihT, pwhhT);
    cudaMemsetAsync(pdeg, 0, (size_t)N * sizeof(float), 0);
    deg_kernel<<<(E + 255) / 256, 256>>>(dst, pdeg, E);

    // out = h = relu(x @ lin0_w^T + b)
    {
        dim3 g(1, (N + 63) / 64);
        gemm_bt<<<g, 256>>>(x, lin0_w, lin0_b, ph, N, DD, 92, 1);
    }
    // H = relu(ea @ nn1_w^T + b)
    {
        dim3 g(HIDC / 64, (E + 63) / 64);
        gemm_bt<<<g, 256>>>(ea, nn1_w, nn1_b, pH, E, HIDC, 41, 1);
    }
    // We = H @ nn2_w^T + b      (dominant GEMM, 67 GFLOP)
    {
        dim3 g((DD * DD) / 64, (E + 63) / 64);
        gemm_bt<<<g, 256>>>(pH, nn2_w, nn2_b, pWe, E, DD * DD, HIDC, 0);
    }

    // --- 2 conv + GRU iterations ---
    for (int c = 0; c < 2; c++) {
        cudaMemsetAsync(pagg, 0, (size_t)N * DD * sizeof(float), 0);
        msg_kernel<<<E, DD>>>(ph, pWe, src, dst, pagg);
        {
            dim3 g(1, (N + 63) / 64);
            gemm_bt<<<g, 256>>>(ph, root_w, conv_b, ptmp, N, DD, DD, 0);
        }
        m_kernel<<<(N * DD + 255) / 256, 256>>>(ptmp, pagg, pdeg, N * DD);
        {
            dim3 g(3, (N + 63) / 64);
            gemm_bt<<<g, 256>>>(ptmp, gru_w_ih, gru_b_ih, pgi, N, 3 * DD, DD, 0);
            gemm_bt<<<g, 256>>>(ph, gru_w_hh, gru_b_hh, pgh, N, 3 * DD, DD, 0);
        }
        gru_kernel<<<(N * DD + 255) / 256, 256>>>(pgi, pgh, ph, N * DD);
    }

    // --- Set2Set ---
    cudaMemsetAsync(pqstar, 0, NSEG * 2 * DD * sizeof(float), 0);
    cudaMemsetAsync(phl, 0, NSEG * DD * sizeof(float), 0);
    cudaMemsetAsync(pcl, 0, NSEG * DD * sizeof(float), 0);
    for (int s = 0; s < 3; s++) {
        lstm_kernel<<<NSEG, 256>>>(pwihT, pwhhT, lstm_b_ih, lstm_b_hh,
                                   pqstar, phl, pcl, pq);
        init_step<<<(NSEG * DD + 255) / 256, 256>>>(pmmax, pdenom, pr);
        escore_kernel<<<(N + 3) / 4, 128>>>(ph, pq, batch, pe, pmmax, N);
        attn_kernel<<<(N + 3) / 4, 128>>>(ph, pe, batch, pmmax, pdenom, pr, N);
        qstar_kernel<<<NSEG, 128>>>(pq, pr, pdenom, pqstar);
    }

    // --- head ---
    {
        dim3 g(1, (NSEG + 63) / 64);
        gemm_bt<<<g, 256>>>(pqstar, lin1_w, lin1_b, py1, NSEG, DD, 2 * DD, 1);
    }
    final_kernel<<<NSEG, 32>>>(py1, lin2_w, lin2_b, out);
}